// round 3
// baseline (speedup 1.0000x reference)
#include <cuda_runtime.h>
#include <math.h>

#define Bsz 4
#define Nn 1024
#define IND 128
#define Dd 512
#define Hh 8
#define HDd 64
#define Ee 4
#define Ll 3
#define BNROWS (Bsz*Nn)   // 4096

// Scratch (device globals: no cudaMalloc allowed)
__device__ float g_h [BNROWS*Dd];
__device__ float g_q [BNROWS*Dd];
__device__ float g_k [BNROWS*Dd];
__device__ float g_v [BNROWS*Dd];
__device__ float g_ao[BNROWS*Dd];

// ---------------------------------------------------------------------------
// Tiled SGEMM: C[M x Nc] = A[M x K] @ W[K x Nc] + bias (+ res)
// BM=128, BN=64, BK=16, 256 threads, 8x4 per-thread tile.
// M=4096 (mult of 128), Nc=512 (mult of 64), K in {128,512} (mult of 16):
// no bounds checks needed.
// ---------------------------------------------------------------------------
template<bool RES>
__global__ __launch_bounds__(256)
void gemm_bias(const float* __restrict__ A, const float* __restrict__ W,
               const float* __restrict__ bias, const float* __restrict__ res,
               float* __restrict__ C, int K, int Nc) {
    __shared__ float As[16][132];   // transposed: As[k][m], padded vs bank conflicts
    __shared__ float Bs[16][68];    // Bs[k][n]

    const int tid = threadIdx.x;
    const int tx = tid & 15;        // 0..15 -> 4 cols each
    const int ty = tid >> 4;        // 0..15 -> 8 rows each
    const int bm = blockIdx.x * 128;
    const int bn = blockIdx.y * 64;

    const int arow = tid >> 2;           // 0..63
    const int acol = (tid & 3) << 2;     // 0,4,8,12
    const int brow = tid >> 4;           // 0..15
    const int bcol = (tid & 15) << 2;    // 0..60

    float acc[8][4];
    #pragma unroll
    for (int a = 0; a < 8; a++)
        #pragma unroll
        for (int c = 0; c < 4; c++) acc[a][c] = 0.f;

    for (int k0 = 0; k0 < K; k0 += 16) {
        __syncthreads();
        #pragma unroll
        for (int p = 0; p < 2; p++) {
            float4 a4 = *(const float4*)(A + (size_t)(bm + arow + p*64)*K + k0 + acol);
            As[acol+0][arow + p*64] = a4.x;
            As[acol+1][arow + p*64] = a4.y;
            As[acol+2][arow + p*64] = a4.z;
            As[acol+3][arow + p*64] = a4.w;
        }
        *(float4*)&Bs[brow][bcol] = *(const float4*)(W + (size_t)(k0 + brow)*Nc + bn + bcol);
        __syncthreads();

        #pragma unroll
        for (int kk = 0; kk < 16; kk++) {
            float av[8], bv[4];
            float4 t0 = *(const float4*)&As[kk][ty*8];
            float4 t1 = *(const float4*)&As[kk][ty*8 + 4];
            float4 t2 = *(const float4*)&Bs[kk][tx*4];
            av[0]=t0.x; av[1]=t0.y; av[2]=t0.z; av[3]=t0.w;
            av[4]=t1.x; av[5]=t1.y; av[6]=t1.z; av[7]=t1.w;
            bv[0]=t2.x; bv[1]=t2.y; bv[2]=t2.z; bv[3]=t2.w;
            #pragma unroll
            for (int a = 0; a < 8; a++)
                #pragma unroll
                for (int c = 0; c < 4; c++)
                    acc[a][c] += av[a] * bv[c];
        }
    }

    const float4 bb4 = *(const float4*)(bias + bn + tx*4);
    #pragma unroll
    for (int a = 0; a < 8; a++) {
        size_t off = (size_t)(bm + ty*8 + a)*Nc + bn + tx*4;
        float4 r;
        r.x = acc[a][0] + bb4.x;
        r.y = acc[a][1] + bb4.y;
        r.z = acc[a][2] + bb4.z;
        r.w = acc[a][3] + bb4.w;
        if (RES) {
            float4 p = *(const float4*)(res + off);
            r.x += p.x; r.y += p.y; r.z += p.z; r.w += p.w;
        }
        *(float4*)(C + off) = r;
    }
}

// ---------------------------------------------------------------------------
// Flash attention with edge bias.
// One CTA per (b, head, i-tile of 64 rows); loops over 16 j-tiles of 64.
// S = (Q*0.125) K^T + (edges . ew_h + eb_h); streaming softmax; O += P V.
// smem: Qs[d][i], Ks[d][j], Vs[j][d], Ps[i][j], all stride 68 floats.
// ---------------------------------------------------------------------------
#define ASTRIDE 68
#define ATTN_SMEM_BYTES (4*64*ASTRIDE*4)

__global__ __launch_bounds__(256)
void attn_kernel(const float* __restrict__ q, const float* __restrict__ k,
                 const float* __restrict__ v, const float* __restrict__ edges,
                 const float* __restrict__ ew, const float* __restrict__ eb,
                 float* __restrict__ ao) {
    extern __shared__ float sm[];
    float* Qs = sm;                    // [64][68] indexed [d][i]
    float* Ks = sm + 64*ASTRIDE;       // [d][j]
    float* Vs = sm + 2*64*ASTRIDE;     // [j][d]
    float* Ps = sm + 3*64*ASTRIDE;     // [i][j]

    const int tid = threadIdx.x;
    const int tx = tid & 15;           // j / d-out groups of 4
    const int ty = tid >> 4;           // i groups of 4
    const int it = blockIdx.x & 15;
    const int hh = (blockIdx.x >> 4) & 7;
    const int bb = blockIdx.x >> 7;
    const int i0 = it * 64;

    const float ew0 = ew[0*Hh + hh], ew1 = ew[1*Hh + hh];
    const float ew2 = ew[2*Hh + hh], ew3 = ew[3*Hh + hh];
    const float ebh = eb[hh];

    const int lrow = tid >> 2;           // 0..63
    const int lcol = (tid & 3) << 2;     // 0,4,8,12

    // Load Q tile transposed, pre-scaled by 1/sqrt(HD)=0.125
    {
        const float* qp = q + ((size_t)(bb*Nn + i0 + lrow))*Dd + hh*HDd;
        #pragma unroll
        for (int p = 0; p < 4; p++) {
            int d = lcol + p*16;
            float4 a4 = *(const float4*)(qp + d);
            Qs[(d+0)*ASTRIDE + lrow] = a4.x * 0.125f;
            Qs[(d+1)*ASTRIDE + lrow] = a4.y * 0.125f;
            Qs[(d+2)*ASTRIDE + lrow] = a4.z * 0.125f;
            Qs[(d+3)*ASTRIDE + lrow] = a4.w * 0.125f;
        }
    }

    float o[4][4];
    float m[4], l[4];
    #pragma unroll
    for (int a = 0; a < 4; a++) {
        m[a] = -1e30f; l[a] = 0.f;
        #pragma unroll
        for (int c = 0; c < 4; c++) o[a][c] = 0.f;
    }

    for (int j0 = 0; j0 < Nn; j0 += 64) {
        __syncthreads();  // previous tile's reads of Ks/Vs/Ps done
        // K transposed + V direct into smem
        {
            const float* kp = k + ((size_t)(bb*Nn + j0 + lrow))*Dd + hh*HDd;
            const float* vp = v + ((size_t)(bb*Nn + j0 + lrow))*Dd + hh*HDd;
            #pragma unroll
            for (int p = 0; p < 4; p++) {
                int d = lcol + p*16;
                float4 a4 = *(const float4*)(kp + d);
                Ks[(d+0)*ASTRIDE + lrow] = a4.x;
                Ks[(d+1)*ASTRIDE + lrow] = a4.y;
                Ks[(d+2)*ASTRIDE + lrow] = a4.z;
                Ks[(d+3)*ASTRIDE + lrow] = a4.w;
                *(float4*)(Vs + lrow*ASTRIDE + d) = *(const float4*)(vp + d);
            }
        }
        // edge bias directly into the S accumulators (overlaps with KV STS)
        float s[4][4];
        #pragma unroll
        for (int a = 0; a < 4; a++) {
            const size_t ibase = ((size_t)bb*Nn + (size_t)(i0 + ty*4 + a))*Nn;
            #pragma unroll
            for (int c = 0; c < 4; c++) {
                float4 e4 = *(const float4*)(edges + (ibase + (size_t)(j0 + tx*4 + c))*Ee);
                s[a][c] = ebh + e4.x*ew0 + e4.y*ew1 + e4.z*ew2 + e4.w*ew3;
            }
        }
        __syncthreads();  // KV tiles ready

        // S += Q K^T  (64 d-steps, 4 at a time)
        #pragma unroll
        for (int db = 0; db < 16; db++) {
            float qa[4][4], kb[4][4];
            #pragma unroll
            for (int dd = 0; dd < 4; dd++) {
                float4 tq = *(const float4*)(Qs + (db*4+dd)*ASTRIDE + ty*4);
                float4 tk = *(const float4*)(Ks + (db*4+dd)*ASTRIDE + tx*4);
                qa[dd][0]=tq.x; qa[dd][1]=tq.y; qa[dd][2]=tq.z; qa[dd][3]=tq.w;
                kb[dd][0]=tk.x; kb[dd][1]=tk.y; kb[dd][2]=tk.z; kb[dd][3]=tk.w;
            }
            #pragma unroll
            for (int dd = 0; dd < 4; dd++)
                #pragma unroll
                for (int a = 0; a < 4; a++)
                    #pragma unroll
                    for (int c = 0; c < 4; c++)
                        s[a][c] += qa[dd][a] * kb[dd][c];
        }

        // streaming softmax (rows owned by the 16 lanes sharing ty)
        #pragma unroll
        for (int a = 0; a < 4; a++) {
            float mt = fmaxf(fmaxf(s[a][0], s[a][1]), fmaxf(s[a][2], s[a][3]));
            #pragma unroll
            for (int off = 8; off >= 1; off >>= 1)
                mt = fmaxf(mt, __shfl_xor_sync(0xffffffffu, mt, off));
            float mnew = fmaxf(m[a], mt);
            float alpha = __expf(m[a] - mnew);
            m[a] = mnew;
            float rs = 0.f;
            #pragma unroll
            for (int c = 0; c < 4; c++) { s[a][c] = __expf(s[a][c] - mnew); rs += s[a][c]; }
            #pragma unroll
            for (int off = 8; off >= 1; off >>= 1)
                rs += __shfl_xor_sync(0xffffffffu, rs, off);
            l[a] = l[a]*alpha + rs;
            #pragma unroll
            for (int c = 0; c < 4; c++) o[a][c] *= alpha;
            float4 pr; pr.x=s[a][0]; pr.y=s[a][1]; pr.z=s[a][2]; pr.w=s[a][3];
            *(float4*)(Ps + (size_t)(ty*4+a)*ASTRIDE + tx*4) = pr;
        }
        __syncthreads();  // Ps complete

        // O += P @ V (64 j-steps, 4 at a time)
        #pragma unroll
        for (int jb = 0; jb < 16; jb++) {
            float pf[4][4], vf[4][4];
            #pragma unroll
            for (int a = 0; a < 4; a++) {
                float4 t = *(const float4*)(Ps + (size_t)(ty*4+a)*ASTRIDE + jb*4);
                pf[a][0]=t.x; pf[a][1]=t.y; pf[a][2]=t.z; pf[a][3]=t.w;
            }
            #pragma unroll
            for (int jj = 0; jj < 4; jj++) {
                float4 t = *(const float4*)(Vs + (size_t)(jb*4+jj)*ASTRIDE + tx*4);
                vf[jj][0]=t.x; vf[jj][1]=t.y; vf[jj][2]=t.z; vf[jj][3]=t.w;
            }
            #pragma unroll
            for (int a = 0; a < 4; a++)
                #pragma unroll
                for (int c = 0; c < 4; c++)
                    o[a][c] += pf[a][0]*vf[0][c] + pf[a][1]*vf[1][c]
                             + pf[a][2]*vf[2][c] + pf[a][3]*vf[3][c];
        }
    }

    #pragma unroll
    for (int a = 0; a < 4; a++) {
        float inv = 1.f / l[a];
        float4 r;
        r.x = o[a][0]*inv; r.y = o[a][1]*inv; r.z = o[a][2]*inv; r.w = o[a][3]*inv;
        *(float4*)(ao + ((size_t)(bb*Nn + i0 + ty*4 + a))*Dd + hh*HDd + tx*4) = r;
    }
}

// ---------------------------------------------------------------------------
// LayerNorm: one block (128 threads) per row of 512.
// ---------------------------------------------------------------------------
__global__ __launch_bounds__(128)
void ln_kernel(const float* __restrict__ h, const float* __restrict__ g,
               const float* __restrict__ b, float* __restrict__ out) {
    const int row = blockIdx.x;
    const int tid = threadIdx.x;
    const float4 x = *(const float4*)(h + (size_t)row*Dd + tid*4);
    float s  = x.x + x.y + x.z + x.w;
    float s2 = x.x*x.x + x.y*x.y + x.z*x.z + x.w*x.w;
    #pragma unroll
    for (int off = 16; off >= 1; off >>= 1) {
        s  += __shfl_xor_sync(0xffffffffu, s,  off);
        s2 += __shfl_xor_sync(0xffffffffu, s2, off);
    }
    __shared__ float ws[4], ws2[4];
    if ((tid & 31) == 0) { ws[tid>>5] = s; ws2[tid>>5] = s2; }
    __syncthreads();
    s  = ws[0] + ws[1] + ws[2] + ws[3];
    s2 = ws2[0] + ws2[1] + ws2[2] + ws2[3];
    const float mu  = s * (1.f/Dd);
    const float var = s2 * (1.f/Dd) - mu*mu;
    const float rstd = rsqrtf(var + 1e-5f);
    const float4 g4 = *(const float4*)(g + tid*4);
    const float4 b4 = *(const float4*)(b + tid*4);
    float4 r;
    r.x = (x.x - mu)*rstd*g4.x + b4.x;
    r.y = (x.y - mu)*rstd*g4.y + b4.y;
    r.z = (x.z - mu)*rstd*g4.z + b4.z;
    r.w = (x.w - mu)*rstd*g4.w + b4.w;
    *(float4*)(out + (size_t)row*Dd + tid*4) = r;
}

// ---------------------------------------------------------------------------
extern "C" void kernel_launch(void* const* d_in, const int* in_sizes, int n_in,
                              void* d_out, int out_size) {
    (void)in_sizes; (void)n_in; (void)out_size;
    const float* x    = (const float*)d_in[0];
    const float* edges= (const float*)d_in[1];
    const float* in_w = (const float*)d_in[2];
    const float* in_b = (const float*)d_in[3];
    const float* qw   = (const float*)d_in[4];
    const float* qb   = (const float*)d_in[5];
    const float* kw   = (const float*)d_in[6];
    const float* kb   = (const float*)d_in[7];
    const float* vw   = (const float*)d_in[8];
    const float* vb   = (const float*)d_in[9];
    const float* ow   = (const float*)d_in[10];
    const float* ob   = (const float*)d_in[11];
    const float* ew   = (const float*)d_in[12];
    const float* eb   = (const float*)d_in[13];
    const float* ln_g = (const float*)d_in[14];
    const float* ln_b = (const float*)d_in[15];
    float* out = (float*)d_out;

    float *h, *q, *k, *v, *ao;
    cudaGetSymbolAddress((void**)&h,  g_h);
    cudaGetSymbolAddress((void**)&q,  g_q);
    cudaGetSymbolAddress((void**)&k,  g_k);
    cudaGetSymbolAddress((void**)&v,  g_v);
    cudaGetSymbolAddress((void**)&ao, g_ao);

    cudaFuncSetAttribute(attn_kernel, cudaFuncAttributeMaxDynamicSharedMemorySize,
                         ATTN_SMEM_BYTES);

    dim3 gg(BNROWS/128, Dd/64);   // (32, 8)

    // h = x @ in_w + in_b
    gemm_bias<false><<<gg, 256>>>(x, in_w, in_b, nullptr, h, IND, Dd);

    for (int l = 0; l < Ll; l++) {
        const size_t wo = (size_t)l*Dd*Dd;
        gemm_bias<false><<<gg, 256>>>(h, qw + wo, qb + l*Dd, nullptr, q, Dd, Dd);
        gemm_bias<false><<<gg, 256>>>(h, kw + wo, kb + l*Dd, nullptr, k, Dd, Dd);
        gemm_bias<false><<<gg, 256>>>(h, vw + wo, vb + l*Dd, nullptr, v, Dd, Dd);
        attn_kernel<<<Bsz*Hh*(Nn/64), 256, ATTN_SMEM_BYTES>>>(
            q, k, v, edges, ew + l*Ee*Hh, eb + l*Hh, ao);
        // h = h + ao @ ow + ob
        gemm_bias<true><<<gg, 256>>>(ao, ow + wo, ob + l*Dd, h, h, Dd, Dd);
    }

    ln_kernel<<<BNROWS, 128>>>(h, ln_g, ln_b, out);
}

// round 4
// speedup vs baseline: 2.2458x; 2.2458x over previous
#include <cuda_runtime.h>
#include <math.h>
#include <stdint.h>

#define Bsz 4
#define Nn 1024
#define IND 128
#define Dd 512
#define Hh 8
#define HDd 64
#define Ee 4
#define Ll 3
#define BNROWS (Bsz*Nn)   // 4096

// Scratch (device globals: no cudaMalloc allowed)
__device__ float g_h [BNROWS*Dd];
__device__ float g_q [BNROWS*Dd];
__device__ float g_k [BNROWS*Dd];
__device__ float g_v [BNROWS*Dd];
__device__ float g_ao[BNROWS*Dd];

// ---------------------------------------------------------------------------
// tf32 helpers
// ---------------------------------------------------------------------------
__device__ __forceinline__ float f2tf(float x) {
    uint32_t u;
    asm("cvt.rna.tf32.f32 %0, %1;" : "=r"(u) : "f"(x));
    return __uint_as_float(u);
}

// D = A(16x8) * B(8x8) + C, tf32 in, fp32 out. a,b hold tf32 bit patterns.
__device__ __forceinline__ void mma8(float* c, float a0, float a1, float a2, float a3,
                                     float b0, float b1) {
    uint32_t A0 = __float_as_uint(a0), A1 = __float_as_uint(a1);
    uint32_t A2 = __float_as_uint(a2), A3 = __float_as_uint(a3);
    uint32_t B0 = __float_as_uint(b0), B1 = __float_as_uint(b1);
    asm volatile(
        "mma.sync.aligned.m16n8k8.row.col.f32.tf32.tf32.f32 "
        "{%0,%1,%2,%3},{%4,%5,%6,%7},{%8,%9},{%0,%1,%2,%3};"
        : "+f"(c[0]), "+f"(c[1]), "+f"(c[2]), "+f"(c[3])
        : "r"(A0), "r"(A1), "r"(A2), "r"(A3), "r"(B0), "r"(B1));
}

// ---------------------------------------------------------------------------
// tf32 tensor-core GEMM: C[M x Nc] = A[M x K] @ W[K x Nc] + bias (+ res)
// CTA tile 128x64, BK=32. 8 warps in 4x2 grid, warp tile 32x32.
// Per warp: 2 m-tiles x 4 n-tiles of m16n8k8.
// As: [128][36] row-major (banks 4g+tg distinct); Bs: [32][72] (banks 8tg+g).
// ---------------------------------------------------------------------------
#define GA_STR 36
#define GB_STR 72

template<bool RES>
__global__ __launch_bounds__(256)
void gemm_tf32(const float* __restrict__ A, const float* __restrict__ W,
               const float* __restrict__ bias, const float* __restrict__ res,
               float* __restrict__ C, int K, int Nc) {
    __shared__ float As[128*GA_STR];
    __shared__ float Bs[32*GB_STR];

    const int tid  = threadIdx.x;
    const int lane = tid & 31;
    const int warp = tid >> 5;
    const int wm   = warp & 3;          // 0..3  (m offset 32*wm)
    const int wn   = warp >> 2;         // 0..1  (n offset 32*wn)
    const int g    = lane >> 2;         // groupID 0..7
    const int tg   = lane & 3;          // thread-in-group 0..3
    const int bm   = blockIdx.x * 128;
    const int bn   = blockIdx.y * 64;

    // staging indices
    const int ar = tid >> 3;            // 0..31 (A rows ar + 32p)
    const int ac = (tid & 7) << 2;      // 0..28
    const int br = tid >> 4;            // 0..15 (W rows br + 16p)
    const int bc = (tid & 15) << 2;     // 0..60

    float acc[2][4][4];
    #pragma unroll
    for (int mt = 0; mt < 2; mt++)
        #pragma unroll
        for (int nt = 0; nt < 4; nt++)
            #pragma unroll
            for (int e = 0; e < 4; e++) acc[mt][nt][e] = 0.f;

    for (int k0 = 0; k0 < K; k0 += 32) {
        __syncthreads();
        #pragma unroll
        for (int p = 0; p < 4; p++) {
            float4 v = *(const float4*)(A + (size_t)(bm + ar + 32*p)*K + k0 + ac);
            float4 t;
            t.x = f2tf(v.x); t.y = f2tf(v.y); t.z = f2tf(v.z); t.w = f2tf(v.w);
            *(float4*)(As + (ar + 32*p)*GA_STR + ac) = t;
        }
        #pragma unroll
        for (int p = 0; p < 2; p++) {
            float4 v = *(const float4*)(W + (size_t)(k0 + br + 16*p)*Nc + bn + bc);
            float4 t;
            t.x = f2tf(v.x); t.y = f2tf(v.y); t.z = f2tf(v.z); t.w = f2tf(v.w);
            *(float4*)(Bs + (br + 16*p)*GB_STR + bc) = t;
        }
        __syncthreads();

        #pragma unroll
        for (int kk = 0; kk < 4; kk++) {
            const int kb = kk * 8;
            float a[2][4];
            #pragma unroll
            for (int mt = 0; mt < 2; mt++) {
                const int r = wm*32 + mt*16;
                a[mt][0] = As[(r + g    )*GA_STR + kb + tg    ];
                a[mt][1] = As[(r + g + 8)*GA_STR + kb + tg    ];
                a[mt][2] = As[(r + g    )*GA_STR + kb + tg + 4];
                a[mt][3] = As[(r + g + 8)*GA_STR + kb + tg + 4];
            }
            float b[4][2];
            #pragma unroll
            for (int nt = 0; nt < 4; nt++) {
                const int cc = wn*32 + nt*8 + g;
                b[nt][0] = Bs[(kb + tg    )*GB_STR + cc];
                b[nt][1] = Bs[(kb + tg + 4)*GB_STR + cc];
            }
            #pragma unroll
            for (int mt = 0; mt < 2; mt++)
                #pragma unroll
                for (int nt = 0; nt < 4; nt++)
                    mma8(acc[mt][nt], a[mt][0], a[mt][1], a[mt][2], a[mt][3],
                         b[nt][0], b[nt][1]);
        }
    }

    // epilogue
    #pragma unroll
    for (int mt = 0; mt < 2; mt++) {
        const int r0 = bm + wm*32 + mt*16 + g;
        #pragma unroll
        for (int nt = 0; nt < 4; nt++) {
            const int cc = bn + wn*32 + nt*8 + 2*tg;
            const float b0 = bias[cc], b1 = bias[cc + 1];
            float2 o0, o1;
            o0.x = acc[mt][nt][0] + b0; o0.y = acc[mt][nt][1] + b1;
            o1.x = acc[mt][nt][2] + b0; o1.y = acc[mt][nt][3] + b1;
            const size_t off0 = (size_t)r0*Nc + cc;
            const size_t off1 = (size_t)(r0 + 8)*Nc + cc;
            if (RES) {
                float2 p0 = *(const float2*)(res + off0);
                float2 p1 = *(const float2*)(res + off1);
                o0.x += p0.x; o0.y += p0.y; o1.x += p1.x; o1.y += p1.y;
            }
            *(float2*)(C + off0) = o0;
            *(float2*)(C + off1) = o1;
        }
    }
}

// ---------------------------------------------------------------------------
// tf32 flash attention with edge bias.
// CTA = (head, 128-row i-tile, batch). 8 warps, warp w owns rows w*16..w*16+15
// (full 64 cols) -> softmax rows live inside one warp (quad shuffles).
// smem: Qs[128][68] (i,d) tf32; Ks[64][72] (d,j) tf32; Vs[64][72] (j,d) tf32;
//       Ps[128][68] (i,j) tf32.
// ---------------------------------------------------------------------------
#define QSTR 68
#define KSTR 72
#define ATTN_SMEM ((128*QSTR + 64*KSTR + 64*KSTR + 128*QSTR)*4)

__global__ __launch_bounds__(256)
void attn_tf32(const float* __restrict__ q, const float* __restrict__ k,
               const float* __restrict__ v, const float* __restrict__ edges,
               const float* __restrict__ ew, const float* __restrict__ eb,
               float* __restrict__ ao) {
    extern __shared__ float sm[];
    float* Qs = sm;                       // [128][QSTR]
    float* Ks = Qs + 128*QSTR;            // [64][KSTR] (d-major)
    float* Vs = Ks + 64*KSTR;             // [64][KSTR] (j-major)
    float* Ps = Vs + 64*KSTR;             // [128][QSTR]

    const int tid  = threadIdx.x;
    const int lane = tid & 31;
    const int w    = tid >> 5;
    const int g    = lane >> 2;
    const int tg   = lane & 3;
    const int hh   = blockIdx.x;
    const int i0   = blockIdx.y * 128;
    const int bb   = blockIdx.z;

    const float ew0 = ew[hh], ew1 = ew[Hh + hh];
    const float ew2 = ew[2*Hh + hh], ew3 = ew[3*Hh + hh];
    const float ebh = eb[hh];

    const int lr = tid >> 2;             // 0..63
    const int lc = (tid & 3) << 2;       // 0,4,8,12

    // Load Q (scaled by 0.125, tf32) : rows lr, lr+64
    #pragma unroll
    for (int rr = 0; rr < 2; rr++) {
        const int r = lr + rr*64;
        const float* qp = q + ((size_t)(bb*Nn + i0 + r))*Dd + hh*HDd;
        #pragma unroll
        for (int p = 0; p < 4; p++) {
            const int d = lc + p*16;
            float4 a = *(const float4*)(qp + d);
            float4 t;
            t.x = f2tf(a.x * 0.125f); t.y = f2tf(a.y * 0.125f);
            t.z = f2tf(a.z * 0.125f); t.w = f2tf(a.w * 0.125f);
            *(float4*)(Qs + r*QSTR + d) = t;
        }
    }

    float o[8][4];
    #pragma unroll
    for (int dt = 0; dt < 8; dt++)
        #pragma unroll
        for (int e = 0; e < 4; e++) o[dt][e] = 0.f;
    float m0 = -1e30f, m1 = -1e30f, l0 = 0.f, l1 = 0.f;

    const int   r0g  = i0 + w*16 + g;                       // global row (c0,c1)
    const size_t eb0 = ((size_t)bb*Nn + r0g)*Nn;            // edges row base (x Ee)
    const size_t eb1 = eb0 + 8*(size_t)Nn;                  // row + 8

    for (int j0 = 0; j0 < Nn; j0 += 64) {
        __syncthreads();   // previous tile's Ks/Vs reads done

        // stage K (transposed, tf32) + V (tf32): one j-row, 4 d-chunks / thread
        {
            const float* kp = k + ((size_t)(bb*Nn + j0 + lr))*Dd + hh*HDd;
            const float* vp = v + ((size_t)(bb*Nn + j0 + lr))*Dd + hh*HDd;
            #pragma unroll
            for (int p = 0; p < 4; p++) {
                const int d = lc + p*16;
                float4 kv = *(const float4*)(kp + d);
                Ks[(d+0)*KSTR + lr] = f2tf(kv.x);
                Ks[(d+1)*KSTR + lr] = f2tf(kv.y);
                Ks[(d+2)*KSTR + lr] = f2tf(kv.z);
                Ks[(d+3)*KSTR + lr] = f2tf(kv.w);
                float4 vv = *(const float4*)(vp + d);
                float4 tv;
                tv.x = f2tf(vv.x); tv.y = f2tf(vv.y);
                tv.z = f2tf(vv.z); tv.w = f2tf(vv.w);
                *(float4*)(Vs + lr*KSTR + d) = tv;
            }
        }

        // edge bias -> S accumulator init (fp32, overlaps with staging)
        float s[8][4];
        #pragma unroll
        for (int nt = 0; nt < 8; nt++) {
            const int jc = j0 + nt*8 + 2*tg;
            float4 e0 = *(const float4*)(edges + (eb0 + jc    )*Ee);
            float4 e1 = *(const float4*)(edges + (eb0 + jc + 1)*Ee);
            float4 e2 = *(const float4*)(edges + (eb1 + jc    )*Ee);
            float4 e3 = *(const float4*)(edges + (eb1 + jc + 1)*Ee);
            s[nt][0] = fmaf(e0.x,ew0, fmaf(e0.y,ew1, fmaf(e0.z,ew2, fmaf(e0.w,ew3, ebh))));
            s[nt][1] = fmaf(e1.x,ew0, fmaf(e1.y,ew1, fmaf(e1.z,ew2, fmaf(e1.w,ew3, ebh))));
            s[nt][2] = fmaf(e2.x,ew0, fmaf(e2.y,ew1, fmaf(e2.z,ew2, fmaf(e2.w,ew3, ebh))));
            s[nt][3] = fmaf(e3.x,ew0, fmaf(e3.y,ew1, fmaf(e3.z,ew2, fmaf(e3.w,ew3, ebh))));
        }
        __syncthreads();   // Ks/Vs ready

        // S += Q K^T
        #pragma unroll
        for (int kb = 0; kb < 64; kb += 8) {
            const float a0 = Qs[(w*16 + g    )*QSTR + kb + tg    ];
            const float a1 = Qs[(w*16 + g + 8)*QSTR + kb + tg    ];
            const float a2 = Qs[(w*16 + g    )*QSTR + kb + tg + 4];
            const float a3 = Qs[(w*16 + g + 8)*QSTR + kb + tg + 4];
            #pragma unroll
            for (int nt = 0; nt < 8; nt++) {
                const float b0 = Ks[(kb + tg    )*KSTR + nt*8 + g];
                const float b1 = Ks[(kb + tg + 4)*KSTR + nt*8 + g];
                mma8(s[nt], a0, a1, a2, a3, b0, b1);
            }
        }

        // online softmax, rows r0 (regs 0,1) and r0+8 (regs 2,3)
        float mt0 = -1e30f, mt1 = -1e30f;
        #pragma unroll
        for (int nt = 0; nt < 8; nt++) {
            mt0 = fmaxf(mt0, fmaxf(s[nt][0], s[nt][1]));
            mt1 = fmaxf(mt1, fmaxf(s[nt][2], s[nt][3]));
        }
        mt0 = fmaxf(mt0, __shfl_xor_sync(0xffffffffu, mt0, 1));
        mt0 = fmaxf(mt0, __shfl_xor_sync(0xffffffffu, mt0, 2));
        mt1 = fmaxf(mt1, __shfl_xor_sync(0xffffffffu, mt1, 1));
        mt1 = fmaxf(mt1, __shfl_xor_sync(0xffffffffu, mt1, 2));
        const float mn0 = fmaxf(m0, mt0), mn1 = fmaxf(m1, mt1);
        const float al0 = __expf(m0 - mn0), al1 = __expf(m1 - mn1);
        m0 = mn0; m1 = mn1;
        float rs0 = 0.f, rs1 = 0.f;
        #pragma unroll
        for (int nt = 0; nt < 8; nt++) {
            s[nt][0] = __expf(s[nt][0] - mn0); rs0 += s[nt][0];
            s[nt][1] = __expf(s[nt][1] - mn0); rs0 += s[nt][1];
            s[nt][2] = __expf(s[nt][2] - mn1); rs1 += s[nt][2];
            s[nt][3] = __expf(s[nt][3] - mn1); rs1 += s[nt][3];
        }
        rs0 += __shfl_xor_sync(0xffffffffu, rs0, 1);
        rs0 += __shfl_xor_sync(0xffffffffu, rs0, 2);
        rs1 += __shfl_xor_sync(0xffffffffu, rs1, 1);
        rs1 += __shfl_xor_sync(0xffffffffu, rs1, 2);
        l0 = l0*al0 + rs0; l1 = l1*al1 + rs1;
        #pragma unroll
        for (int dt = 0; dt < 8; dt++) {
            o[dt][0] *= al0; o[dt][1] *= al0;
            o[dt][2] *= al1; o[dt][3] *= al1;
        }

        // store P (tf32) to smem — written & read by the SAME warp
        #pragma unroll
        for (int nt = 0; nt < 8; nt++) {
            float2 p0, p1;
            p0.x = f2tf(s[nt][0]); p0.y = f2tf(s[nt][1]);
            p1.x = f2tf(s[nt][2]); p1.y = f2tf(s[nt][3]);
            *(float2*)(Ps + (w*16 + g    )*QSTR + nt*8 + 2*tg) = p0;
            *(float2*)(Ps + (w*16 + g + 8)*QSTR + nt*8 + 2*tg) = p1;
        }
        __syncwarp();

        // O += P @ V
        #pragma unroll
        for (int kb = 0; kb < 64; kb += 8) {
            const float a0 = Ps[(w*16 + g    )*QSTR + kb + tg    ];
            const float a1 = Ps[(w*16 + g + 8)*QSTR + kb + tg    ];
            const float a2 = Ps[(w*16 + g    )*QSTR + kb + tg + 4];
            const float a3 = Ps[(w*16 + g + 8)*QSTR + kb + tg + 4];
            #pragma unroll
            for (int dt = 0; dt < 8; dt++) {
                const float b0 = Vs[(kb + tg    )*KSTR + dt*8 + g];
                const float b1 = Vs[(kb + tg + 4)*KSTR + dt*8 + g];
                mma8(o[dt], a0, a1, a2, a3, b0, b1);
            }
        }
    }

    // epilogue: divide by l, write ao[(b, i)][h*64 + d]
    const float inv0 = 1.f / l0, inv1 = 1.f / l1;
    float* op0 = ao + ((size_t)(bb*Nn + r0g    ))*Dd + hh*HDd;
    float* op1 = ao + ((size_t)(bb*Nn + r0g + 8))*Dd + hh*HDd;
    #pragma unroll
    for (int dt = 0; dt < 8; dt++) {
        const int dc = dt*8 + 2*tg;
        float2 o0, o1;
        o0.x = o[dt][0]*inv0; o0.y = o[dt][1]*inv0;
        o1.x = o[dt][2]*inv1; o1.y = o[dt][3]*inv1;
        *(float2*)(op0 + dc) = o0;
        *(float2*)(op1 + dc) = o1;
    }
}

// ---------------------------------------------------------------------------
// LayerNorm: one block (128 threads) per row of 512.
// ---------------------------------------------------------------------------
__global__ __launch_bounds__(128)
void ln_kernel(const float* __restrict__ h, const float* __restrict__ g,
               const float* __restrict__ b, float* __restrict__ out) {
    const int row = blockIdx.x;
    const int tid = threadIdx.x;
    const float4 x = *(const float4*)(h + (size_t)row*Dd + tid*4);
    float s  = x.x + x.y + x.z + x.w;
    float s2 = x.x*x.x + x.y*x.y + x.z*x.z + x.w*x.w;
    #pragma unroll
    for (int off = 16; off >= 1; off >>= 1) {
        s  += __shfl_xor_sync(0xffffffffu, s,  off);
        s2 += __shfl_xor_sync(0xffffffffu, s2, off);
    }
    __shared__ float ws[4], ws2[4];
    if ((tid & 31) == 0) { ws[tid>>5] = s; ws2[tid>>5] = s2; }
    __syncthreads();
    s  = ws[0] + ws[1] + ws[2] + ws[3];
    s2 = ws2[0] + ws2[1] + ws2[2] + ws2[3];
    const float mu  = s * (1.f/Dd);
    const float var = s2 * (1.f/Dd) - mu*mu;
    const float rstd = rsqrtf(var + 1e-5f);
    const float4 g4 = *(const float4*)(g + tid*4);
    const float4 b4 = *(const float4*)(b + tid*4);
    float4 r;
    r.x = (x.x - mu)*rstd*g4.x + b4.x;
    r.y = (x.y - mu)*rstd*g4.y + b4.y;
    r.z = (x.z - mu)*rstd*g4.z + b4.z;
    r.w = (x.w - mu)*rstd*g4.w + b4.w;
    *(float4*)(out + (size_t)row*Dd + tid*4) = r;
}

// ---------------------------------------------------------------------------
extern "C" void kernel_launch(void* const* d_in, const int* in_sizes, int n_in,
                              void* d_out, int out_size) {
    (void)in_sizes; (void)n_in; (void)out_size;
    const float* x    = (const float*)d_in[0];
    const float* edges= (const float*)d_in[1];
    const float* in_w = (const float*)d_in[2];
    const float* in_b = (const float*)d_in[3];
    const float* qw   = (const float*)d_in[4];
    const float* qb   = (const float*)d_in[5];
    const float* kw   = (const float*)d_in[6];
    const float* kb   = (const float*)d_in[7];
    const float* vw   = (const float*)d_in[8];
    const float* vb   = (const float*)d_in[9];
    const float* ow   = (const float*)d_in[10];
    const float* ob   = (const float*)d_in[11];
    const float* ew   = (const float*)d_in[12];
    const float* eb   = (const float*)d_in[13];
    const float* ln_g = (const float*)d_in[14];
    const float* ln_b = (const float*)d_in[15];
    float* out = (float*)d_out;

    float *h, *q, *k, *v, *ao;
    cudaGetSymbolAddress((void**)&h,  g_h);
    cudaGetSymbolAddress((void**)&q,  g_q);
    cudaGetSymbolAddress((void**)&k,  g_k);
    cudaGetSymbolAddress((void**)&v,  g_v);
    cudaGetSymbolAddress((void**)&ao, g_ao);

    cudaFuncSetAttribute(attn_tf32, cudaFuncAttributeMaxDynamicSharedMemorySize,
                         ATTN_SMEM);

    dim3 gg(BNROWS/128, Dd/64);            // (32, 8)
    dim3 ag(Hh, Nn/128, Bsz);              // (8, 8, 4)

    // h = x @ in_w + in_b
    gemm_tf32<false><<<gg, 256>>>(x, in_w, in_b, nullptr, h, IND, Dd);

    for (int l = 0; l < Ll; l++) {
        const size_t wo = (size_t)l*Dd*Dd;
        gemm_tf32<false><<<gg, 256>>>(h, qw + wo, qb + l*Dd, nullptr, q, Dd, Dd);
        gemm_tf32<false><<<gg, 256>>>(h, kw + wo, kb + l*Dd, nullptr, k, Dd, Dd);
        gemm_tf32<false><<<gg, 256>>>(h, vw + wo, vb + l*Dd, nullptr, v, Dd, Dd);
        attn_tf32<<<ag, 256, ATTN_SMEM>>>(q, k, v, edges,
                                          ew + l*Ee*Hh, eb + l*Hh, ao);
        // h = h + ao @ ow + ob
        gemm_tf32<true><<<gg, 256>>>(ao, ow + wo, ob + l*Dd, h, h, Dd, Dd);
    }

    ln_kernel<<<BNROWS, 128>>>(h, ln_g, ln_b, out);
}